// round 4
// baseline (speedup 1.0000x reference)
#include <cuda_runtime.h>
#include <cstdint>

// ---------------------------------------------------------------------------
// RBF perturbed sphere attractor:
//   out[i] = x[i]*(1-||x[i]||) + sum_j exp(-||x[i]-c[j]||^2 / (2*L^2)) * coef[j]
// N = ~100000 points, M = 3375 centers, L = 0.3.
//
// exp(-d2/0.18) == exp2(KNEG*(x2 + c2 - 2 x.c)),  KNEG = -log2(e)/0.18
// Per-center precompute: cs = (-2*KNEG)*c  (3 floats), a = KNEG*c2
// Per-point precompute:  b = KNEG*x2
// arg = x0*cs0 + x1*cs1 + x2*cs2 + a + b   -> ex2.approx
//
// Packed over CENTER PAIRS with fma.rn.f32x2 so the fma-pipe cost halves;
// center data is stored pre-packed in SMEM (ld.shared.v2.b64, no dup movs).
// MUFU.EX2 is the expected binding pipe (~142k cyc/SM floor).
// ---------------------------------------------------------------------------

#define TPB   128
#define PTS   2            // points per thread
#define TILE  512          // centers per smem tile (even)
#define PAIRS (TILE / 2)

__device__ __forceinline__ uint64_t pk2(float lo, float hi) {
    uint64_t r;
    asm("mov.b64 %0, {%1, %2};" : "=l"(r) : "f"(lo), "f"(hi));
    return r;
}
__device__ __forceinline__ void up2(uint64_t v, float& lo, float& hi) {
    asm("mov.b64 {%0, %1}, %2;" : "=f"(lo), "=f"(hi) : "l"(v));
}
__device__ __forceinline__ uint64_t fma2(uint64_t a, uint64_t b, uint64_t c) {
    uint64_t d;
    asm("fma.rn.f32x2 %0, %1, %2, %3;" : "=l"(d) : "l"(a), "l"(b), "l"(c));
    return d;
}
__device__ __forceinline__ uint64_t add2(uint64_t a, uint64_t b) {
    uint64_t d;
    asm("add.rn.f32x2 %0, %1, %2;" : "=l"(d) : "l"(a), "l"(b));
    return d;
}
__device__ __forceinline__ float ex2f(float x) {
    float r;
    asm("ex2.approx.f32 %0, %1;" : "=f"(r) : "f"(x));
    return r;
}

__global__ __launch_bounds__(TPB, 3)
void rbf_attractor_kernel(const float* __restrict__ x,
                          const float* __restrict__ centers,
                          const float* __restrict__ cu,
                          const float* __restrict__ cv,
                          const float* __restrict__ cw,
                          float* __restrict__ out,
                          int N, int M)
{
    // Per center-pair: [CS0|CS0'][CS1|CS1'][CS2|CS2'][A|A'][CU|CU'][CV|CV'][CW|CW'][pad]
    __shared__ __align__(16) uint64_t s[PAIRS * 8];

    const float KNEG = -8.01497245f;   // -log2(e) / (2 * 0.3^2)
    const float G    = 16.0299449f;    // -2 * KNEG

    const int i0 = blockIdx.x * (TPB * PTS) + threadIdx.x;
    const int i1 = i0 + TPB;

    float x00 = 0.f, x01 = 0.f, x02 = 0.f;
    float x10 = 0.f, x11 = 0.f, x12 = 0.f;
    if (i0 < N) { x00 = x[3 * i0]; x01 = x[3 * i0 + 1]; x02 = x[3 * i0 + 2]; }
    if (i1 < N) { x10 = x[3 * i1]; x11 = x[3 * i1 + 1]; x12 = x[3 * i1 + 2]; }

    const float xs0 = x00 * x00 + x01 * x01 + x02 * x02;
    const float xs1 = x10 * x10 + x11 * x11 + x12 * x12;
    const float b0  = KNEG * xs0;
    const float b1  = KNEG * xs1;

    // Loop-invariant duplicated packs (point value in both halves)
    const uint64_t X00 = pk2(x00, x00), X01 = pk2(x01, x01), X02 = pk2(x02, x02);
    const uint64_t X10 = pk2(x10, x10), X11 = pk2(x11, x11), X12 = pk2(x12, x12);
    const uint64_t B0  = pk2(b0, b0),   B1  = pk2(b1, b1);

    // Packed accumulators: lo half sums even centers, hi half odd centers
    uint64_t aU0 = 0, aV0 = 0, aW0 = 0;
    uint64_t aU1 = 0, aV1 = 0, aW1 = 0;

    for (int base = 0; base < M; base += TILE) {
        // ---- stage + transform one tile of centers into packed smem ----
        for (int t = threadIdx.x; t < PAIRS; t += TPB) {
            const int ja = base + 2 * t;
            const int jb = ja + 1;
            float ca0 = 0.f, ca1 = 0.f, ca2 = 0.f, ua = 0.f, va = 0.f, wa = 0.f;
            float cb0 = 0.f, cb1 = 0.f, cb2 = 0.f, ub = 0.f, vb = 0.f, wb = 0.f;
            if (ja < M) {
                ca0 = centers[3 * ja]; ca1 = centers[3 * ja + 1]; ca2 = centers[3 * ja + 2];
                ua = cu[ja]; va = cv[ja]; wa = cw[ja];
            }
            if (jb < M) {
                cb0 = centers[3 * jb]; cb1 = centers[3 * jb + 1]; cb2 = centers[3 * jb + 2];
                ub = cu[jb]; vb = cv[jb]; wb = cw[jb];
            }
            // padded slots: c=0, coeff=0 -> phi*coef == 0 exactly, no inf/nan
            const float aa = KNEG * (ca0 * ca0 + ca1 * ca1 + ca2 * ca2);
            const float ab = KNEG * (cb0 * cb0 + cb1 * cb1 + cb2 * cb2);
            uint64_t* p = &s[t * 8];
            p[0] = pk2(G * ca0, G * cb0);
            p[1] = pk2(G * ca1, G * cb1);
            p[2] = pk2(G * ca2, G * cb2);
            p[3] = pk2(aa, ab);
            p[4] = pk2(ua, ub);
            p[5] = pk2(va, vb);
            p[6] = pk2(wa, wb);
            p[7] = 0;
        }
        __syncthreads();

        // ---- main loop: 2 centers x 2 points per iteration ----
        #pragma unroll 4
        for (int t = 0; t < PAIRS; ++t) {
            const uint64_t* p = &s[t * 8];
            const ulonglong2 q0 = *reinterpret_cast<const ulonglong2*>(p + 0); // CS0, CS1
            const ulonglong2 q1 = *reinterpret_cast<const ulonglong2*>(p + 2); // CS2, A
            const ulonglong2 q2 = *reinterpret_cast<const ulonglong2*>(p + 4); // CU, CV
            const uint64_t   CW = p[6];

            // point 0
            uint64_t t0 = fma2(X00, q0.x, q1.y);
            t0 = fma2(X01, q0.y, t0);
            t0 = fma2(X02, q1.x, t0);
            t0 = add2(t0, B0);
            float l0, h0; up2(t0, l0, h0);
            const uint64_t P0 = pk2(ex2f(l0), ex2f(h0));
            aU0 = fma2(P0, q2.x, aU0);
            aV0 = fma2(P0, q2.y, aV0);
            aW0 = fma2(P0, CW, aW0);

            // point 1
            uint64_t t1 = fma2(X10, q0.x, q1.y);
            t1 = fma2(X11, q0.y, t1);
            t1 = fma2(X12, q1.x, t1);
            t1 = add2(t1, B1);
            float l1, h1; up2(t1, l1, h1);
            const uint64_t P1 = pk2(ex2f(l1), ex2f(h1));
            aU1 = fma2(P1, q2.x, aU1);
            aV1 = fma2(P1, q2.y, aV1);
            aW1 = fma2(P1, CW, aW1);
        }
        __syncthreads();
    }

    if (i0 < N) {
        float ul, uh, vl, vh, wl, wh;
        up2(aU0, ul, uh); up2(aV0, vl, vh); up2(aW0, wl, wh);
        const float f = 1.0f - sqrtf(xs0);
        out[3 * i0]     = fmaf(x00, f, ul + uh);
        out[3 * i0 + 1] = fmaf(x01, f, vl + vh);
        out[3 * i0 + 2] = fmaf(x02, f, wl + wh);
    }
    if (i1 < N) {
        float ul, uh, vl, vh, wl, wh;
        up2(aU1, ul, uh); up2(aV1, vl, vh); up2(aW1, wl, wh);
        const float f = 1.0f - sqrtf(xs1);
        out[3 * i1]     = fmaf(x10, f, ul + uh);
        out[3 * i1 + 1] = fmaf(x11, f, vl + vh);
        out[3 * i1 + 2] = fmaf(x12, f, wl + wh);
    }
}

extern "C" void kernel_launch(void* const* d_in, const int* in_sizes, int n_in,
                              void* d_out, int out_size)
{
    const float* x       = (const float*)d_in[0];  // (N,3)
    const float* centers = (const float*)d_in[1];  // (M,3)
    const float* cu      = (const float*)d_in[2];  // (M,)
    const float* cv      = (const float*)d_in[3];  // (M,)
    const float* cw      = (const float*)d_in[4];  // (M,)
    float* out = (float*)d_out;

    const int N = in_sizes[0] / 3;
    const int M = in_sizes[2];

    const int pts_per_block = TPB * PTS;
    const int blocks = (N + pts_per_block - 1) / pts_per_block;
    rbf_attractor_kernel<<<blocks, TPB>>>(x, centers, cu, cv, cw, out, N, M);
}